// round 8
// baseline (speedup 1.0000x reference)
#include <cuda_runtime.h>
#include <cuda_bf16.h>
#include <math.h>
#include <math_constants.h>
#include <cstdint>

#define Bn  16
#define Cn  684
#define Hn  32
#define Wn  128
#define HIDn 256
#define An  512
#define HWn 4096
#define NTAP 121

// ---- scratch (device globals; no allocation allowed) ----
__device__ float    g_query[Bn * An];            // [b][a]
__device__ uint32_t g_weffb[An * 64];            // bf16x2 pairs: [a][tap-pair]
__device__ uint16_t g_X[(size_t)Bn * Hn * 128 * 136];  // im2col, padded rows (LDX=136)
__device__ float    g_epart[2 * Bn * HWn];       // [half][b][pos]
__device__ float    g_energy[Bn * HWn];
__device__ float    g_alpha[Bn * HWn];
__device__ float    g_pm[Bn * 4], g_ps[Bn * 4];

// k_energy SMEM layout (bytes)
#define LDX 136
#define LDW 136
#define SM_X 0
#define SM_W 34816
#define SM_QWA 104448
#define SM_TOT 106496

__device__ __forceinline__ float fast_tanh(float x) {
    float y;
    asm("tanh.approx.f32 %0, %1;" : "=f"(y) : "f"(x));
    return y;
}
__device__ __forceinline__ uint32_t smem_u32(const void* p) {
    uint32_t a;
    asm("{ .reg .u64 t; cvta.to.shared.u64 t, %1; cvt.u32.u64 %0, t; }" : "=r"(a) : "l"(p));
    return a;
}

// ---------------- query = hidden @ Wh^T + bh ----------------
__global__ void k_query(const float* __restrict__ hidden,
                        const float* __restrict__ Wh,
                        const float* __restrict__ bh) {
    __shared__ float sh[HIDn];
    const int b = blockIdx.x, tid = threadIdx.x;
    if (tid < HIDn) sh[tid] = hidden[b * HIDn + tid];
    __syncthreads();
    for (int a = tid; a < An; a += 256) {
        float s = bh[a];
        const float* w = Wh + (size_t)a * HIDn;
        #pragma unroll 8
        for (int k = 0; k < HIDn; k++) s = fmaf(w[k], sh[k], s);
        g_query[b * An + a] = s;
    }
}

// ---------------- Weff[a][tap] = sum_k Wattn[a][k]*Wconv[k][tap] -> bf16 pairs ----------------
__global__ void k_weff(const float* __restrict__ Wattn,
                       const float* __restrict__ Wconv) {
    __shared__ float sa[4 * 512];
    const int chunk = blockIdx.x, tid = threadIdx.x;   // 128 chunks x 4 a-rows
    for (int i = tid; i < 4 * 512; i += 256)
        sa[i] = Wattn[(size_t)chunk * 4 * 512 + i];
    __syncthreads();
    const int al = tid >> 6, pr = tid & 63;
    float v0 = 0.f, v1 = 0.f;
    const int t0 = pr * 2, t1 = pr * 2 + 1;
    if (t0 < NTAP) {
        #pragma unroll 8
        for (int k = 0; k < 512; k++)
            v0 = fmaf(sa[al * 512 + k], __ldg(&Wconv[(size_t)k * NTAP + t0]), v0);
    }
    if (t1 < NTAP) {
        #pragma unroll 8
        for (int k = 0; k < 512; k++)
            v1 = fmaf(sa[al * 512 + k], __ldg(&Wconv[(size_t)k * NTAP + t1]), v1);
    }
    uint32_t lo = (uint32_t)__bfloat16_as_ushort(__float2bfloat16(v0));
    uint32_t hi = (uint32_t)__bfloat16_as_ushort(__float2bfloat16(v1));
    g_weffb[(chunk * 4 + al) * 64 + pr] = lo | (hi << 16);
}

// ---------------- im2col staging: X[b,h][128 pos][128 taps] bf16 (padded LDX) ----------------
__global__ void k_im2col(const float* __restrict__ asum) {
    const int h = blockIdx.x, b = blockIdx.y, tid = threadIdx.x;
    const float* arow = asum + (size_t)b * HWn;
    uint32_t* dst = (uint32_t*)(g_X + ((size_t)(b * Hn + h)) * 128 * LDX);
    for (int o = tid; o < 128 * 64; o += 256) {
        int mm = o >> 6, pr = o & 63;
        uint32_t packed = 0;
        #pragma unroll
        for (int hf = 0; hf < 2; hf++) {
            int k = pr * 2 + hf;
            float v = 0.f;
            if (k < NTAP) {
                int i = k / 11, j = k % 11;
                int gh = h - 5 + i, gw = mm - 5 + j;
                if (gh >= 0 && gh < Hn && gw >= 0 && gw < Wn)
                    v = arow[gh * Wn + gw];
            }
            packed |= ((uint32_t)__bfloat16_as_ushort(__float2bfloat16(v))) << (16 * hf);
        }
        dst[mm * (LDX / 2) + pr] = packed;
    }
}

// ---------------- energy: mma.sync m16n8k16, pipelined, low-register ----------------
// grid (2 a-halves, H, B), 256 threads (8 warps). Warp wid owns positions [16*wid, 16*wid+16).
__global__ void __launch_bounds__(256, 2) k_energy(
    const float* __restrict__ cft,     // [b, A, h, w]
    const float* __restrict__ cmt,     // [b, h, w, A]
    const float* __restrict__ walpha)  // [A]
{
    extern __shared__ char smem[];
    __nv_bfloat16* Xsm = (__nv_bfloat16*)(smem + SM_X);
    __nv_bfloat16* Wsm = (__nv_bfloat16*)(smem + SM_W);
    float2*        QWA = (float2*)(smem + SM_QWA);

    const int half = blockIdx.x, h = blockIdx.y, b = blockIdx.z;
    const int tid = threadIdx.x, wid = tid >> 5, lane = tid & 31;
    const int g = lane >> 2, tig = lane & 3;

    // ---- stage X: plain uint4 copy of pre-built im2col tile (34816 B) ----
    {
        const uint4* src = (const uint4*)(g_X + ((size_t)(b * Hn + h)) * 128 * LDX);
        uint4* dst = (uint4*)Xsm;
        #pragma unroll
        for (int o = tid; o < 2176; o += 256) dst[o] = src[o];
    }
    // ---- stage W half: 256 a-rows x 128 taps bf16 ----
    const uint4* wsrc = (const uint4*)(g_weffb + (size_t)half * 256 * 64);
    for (int o = tid; o < 4096; o += 256) {
        int a = o >> 4, q = o & 15;
        *(uint4*)((char*)Wsm + a * (LDW * 2) + q * 16) = wsrc[o];
    }
    // ---- stage (query, walpha) pairs for this a-half ----
    if (tid < 256)
        QWA[tid] = make_float2(g_query[b * An + half * 256 + tid], walpha[half * 256 + tid]);
    __syncthreads();

    // ---- persistent B fragments for nh=0 only (16 regs); nh=1 reloaded per kk ----
    const int pos0 = wid * 16;
    uint32_t bf0[8][2];
    {
        const char* xrow = (const char*)Xsm + (pos0 + g) * (LDX * 2);
        #pragma unroll
        for (int kk = 0; kk < 8; kk++) {
            bf0[kk][0] = *(const uint32_t*)(xrow + (kk * 16 + tig * 2) * 2);
            bf0[kk][1] = *(const uint32_t*)(xrow + (kk * 16 + tig * 2 + 8) * 2);
        }
    }
    const char* xrow1 = (const char*)Xsm + (pos0 + 8 + g) * (LDX * 2);

    const uint32_t a_base = smem_u32(Wsm) + (uint32_t)(lane & 15) * (LDW * 2) + (uint32_t)(lane >> 4) * 16;

    const float* cft_b = cft + ((size_t)b * An + half * 256) * (Hn * Wn) + h * Wn;
    const float* cmt_b = cmt + (((size_t)b * Hn + h) * Wn) * An + half * 256;
    const size_t HW = (size_t)Hn * Wn;

    // double-buffered epilogue operands
    float2 cfb[2][2][2];   // [buf][nh][aoff/8]
    float  cmb[2][2][4];   // [buf][nh][c]

    auto load_ops = [&](int buf, int A0L) {
        #pragma unroll
        for (int nh = 0; nh < 2; nh++) {
            const float* p = cft_b + (size_t)(A0L + g) * HW + pos0 + nh * 8 + tig * 2;
            cfb[buf][nh][0] = *(const float2*)p;
            cfb[buf][nh][1] = *(const float2*)(p + 8 * HW);
        }
        #pragma unroll
        for (int nh = 0; nh < 2; nh++) {
            const float* p = cmt_b + (size_t)(pos0 + nh * 8 + tig * 2) * An + A0L + g;
            cmb[buf][nh][0] = __ldg(p);
            cmb[buf][nh][1] = __ldg(p + An);
            cmb[buf][nh][2] = __ldg(p + 8);
            cmb[buf][nh][3] = __ldg(p + An + 8);
        }
    };

    load_ops(0, 0);   // prologue

    float epos[4] = {0.f, 0.f, 0.f, 0.f};

    #pragma unroll
    for (int mt = 0; mt < 16; mt++) {
        const int A0 = mt * 16;
        const int cur = mt & 1, nxt = cur ^ 1;

        load_ops(nxt, (mt < 15) ? A0 + 16 : A0);

        const float2 qw0 = QWA[A0 + g], qw1 = QWA[A0 + g + 8];

        float c0[4] = {0.f, 0.f, 0.f, 0.f};
        float c1[4] = {0.f, 0.f, 0.f, 0.f};
        #pragma unroll
        for (int kk = 0; kk < 8; kk++) {
            uint32_t a0r, a1r, a2r, a3r;
            uint32_t addr = a_base + (uint32_t)A0 * (LDW * 2) + (uint32_t)(kk * 32);
            asm volatile("ldmatrix.sync.aligned.m8n8.x4.shared.b16 {%0,%1,%2,%3}, [%4];"
                         : "=r"(a0r), "=r"(a1r), "=r"(a2r), "=r"(a3r) : "r"(addr));
            asm volatile("mma.sync.aligned.m16n8k16.row.col.f32.bf16.bf16.f32 "
                         "{%0,%1,%2,%3}, {%4,%5,%6,%7}, {%8,%9}, {%0,%1,%2,%3};"
                         : "+f"(c0[0]), "+f"(c0[1]), "+f"(c0[2]), "+f"(c0[3])
                         : "r"(a0r), "r"(a1r), "r"(a2r), "r"(a3r),
                           "r"(bf0[kk][0]), "r"(bf0[kk][1]));
            uint32_t b1a = *(const uint32_t*)(xrow1 + (kk * 16 + tig * 2) * 2);
            uint32_t b1b = *(const uint32_t*)(xrow1 + (kk * 16 + tig * 2 + 8) * 2);
            asm volatile("mma.sync.aligned.m16n8k16.row.col.f32.bf16.bf16.f32 "
                         "{%0,%1,%2,%3}, {%4,%5,%6,%7}, {%8,%9}, {%0,%1,%2,%3};"
                         : "+f"(c1[0]), "+f"(c1[1]), "+f"(c1[2]), "+f"(c1[3])
                         : "r"(a0r), "r"(a1r), "r"(a2r), "r"(a3r),
                           "r"(b1a), "r"(b1b));
        }

        // register-resident epilogue on buffer 'cur'
        {
            float s;
            s = c0[0] + cfb[cur][0][0].x + cmb[cur][0][0] + qw0.x; epos[0] = fmaf(qw0.y, fast_tanh(s), epos[0]);
            s = c0[1] + cfb[cur][0][0].y + cmb[cur][0][1] + qw0.x; epos[1] = fmaf(qw0.y, fast_tanh(s), epos[1]);
            s = c0[2] + cfb[cur][0][1].x + cmb[cur][0][2] + qw1.x; epos[0] = fmaf(qw1.y, fast_tanh(s), epos[0]);
            s = c0[3] + cfb[cur][0][1].y + cmb[cur][0][3] + qw1.x; epos[1] = fmaf(qw1.y, fast_tanh(s), epos[1]);
            s = c1[0] + cfb[cur][1][0].x + cmb[cur][1][0] + qw0.x; epos[2] = fmaf(qw0.y, fast_tanh(s), epos[2]);
            s = c1[1] + cfb[cur][1][0].y + cmb[cur][1][1] + qw0.x; epos[3] = fmaf(qw0.y, fast_tanh(s), epos[3]);
            s = c1[2] + cfb[cur][1][1].x + cmb[cur][1][2] + qw1.x; epos[2] = fmaf(qw1.y, fast_tanh(s), epos[2]);
            s = c1[3] + cfb[cur][1][1].y + cmb[cur][1][3] + qw1.x; epos[3] = fmaf(qw1.y, fast_tanh(s), epos[3]);
        }
    }

    // reduce over the 8 g-lanes (lane bits 2-4)
    #pragma unroll
    for (int j = 0; j < 4; j++) {
        epos[j] += __shfl_xor_sync(0xffffffffu, epos[j], 4);
        epos[j] += __shfl_xor_sync(0xffffffffu, epos[j], 8);
        epos[j] += __shfl_xor_sync(0xffffffffu, epos[j], 16);
    }
    if (lane < 4) {
        float* ep = g_epart + ((size_t)half * Bn + b) * HWn + h * Wn + pos0;
        ep[tig * 2]         = epos[0];
        ep[tig * 2 + 1]     = epos[1];
        ep[8 + tig * 2]     = epos[2];
        ep[8 + tig * 2 + 1] = epos[3];
    }
}

// ---------------- softmax stage 1 ----------------
__global__ void k_sm1(const int* __restrict__ mask) {
    __shared__ float red[256];
    const int b = blockIdx.x, qt = blockIdx.y, tid = threadIdx.x;
    const int p0 = qt * 1024;

    float e4[4];
    float mx = -CUDART_INF_F;
    #pragma unroll
    for (int i = 0; i < 4; i++) {
        int p = p0 + i * 256 + tid;
        float e = g_epart[b * HWn + p] + g_epart[(Bn + b) * HWn + p];
        if (mask[b * HWn + p] == 0) e = -CUDART_INF_F;
        e4[i] = e;
        g_energy[b * HWn + p] = e;
        mx = fmaxf(mx, e);
    }
    red[tid] = mx; __syncthreads();
    for (int s = 128; s; s >>= 1) {
        if (tid < s) red[tid] = fmaxf(red[tid], red[tid + s]);
        __syncthreads();
    }
    mx = red[0]; __syncthreads();

    float sum = 0.f;
    #pragma unroll
    for (int i = 0; i < 4; i++) sum += __expf(e4[i] - mx);
    red[tid] = sum; __syncthreads();
    for (int s = 128; s; s >>= 1) {
        if (tid < s) red[tid] += red[tid + s];
        __syncthreads();
    }
    if (tid == 0) { g_pm[b * 4 + qt] = mx; g_ps[b * 4 + qt] = red[0]; }
}

// ---------------- softmax stage 2 ----------------
__global__ void k_sm2(const float* __restrict__ asum, float* __restrict__ out) {
    const int b = blockIdx.x, qt = blockIdx.y, tid = threadIdx.x;
    const int p0 = qt * 1024;

    float m0 = g_pm[b * 4 + 0], m1 = g_pm[b * 4 + 1];
    float m2 = g_pm[b * 4 + 2], m3 = g_pm[b * 4 + 3];
    float m = fmaxf(fmaxf(m0, m1), fmaxf(m2, m3));
    float s = g_ps[b * 4 + 0] * __expf(m0 - m) + g_ps[b * 4 + 1] * __expf(m1 - m)
            + g_ps[b * 4 + 2] * __expf(m2 - m) + g_ps[b * 4 + 3] * __expf(m3 - m);
    const float inv = 1.f / s;

    float* out_alpha = out + Bn * Cn;
    float* out_asum  = out + Bn * Cn + Bn * HWn;
    #pragma unroll
    for (int i = 0; i < 4; i++) {
        int p = p0 + i * 256 + tid;
        float al = __expf(g_energy[b * HWn + p] - m) * inv;
        g_alpha[b * HWn + p] = al;
        out_alpha[b * HWn + p] = al;
        out_asum[b * HWn + p] = al + asum[b * HWn + p];
    }
}

// ---------------- context ----------------
__global__ void k_context(const float* __restrict__ cnn,
                          float* __restrict__ out) {
    const int c = blockIdx.x, b = blockIdx.y, tid = threadIdx.x;
    const float4* row = (const float4*)(cnn + ((size_t)b * Cn + c) * HWn);
    const float4* al  = (const float4*)(g_alpha + b * HWn);
    float s = 0.f;
    #pragma unroll
    for (int it = 0; it < 4; it++) {
        int p = it * 256 + tid;
        float4 r = row[p], a = al[p];
        s = fmaf(a.x, r.x, s); s = fmaf(a.y, r.y, s);
        s = fmaf(a.z, r.z, s); s = fmaf(a.w, r.w, s);
    }
    #pragma unroll
    for (int off = 16; off; off >>= 1)
        s += __shfl_xor_sync(0xffffffffu, s, off);
    __shared__ float red[8];
    if ((tid & 31) == 0) red[tid >> 5] = s;
    __syncthreads();
    if (tid == 0) {
        float t = red[0] + red[1] + red[2] + red[3]
                + red[4] + red[5] + red[6] + red[7];
        out[b * Cn + c] = t;
    }
}

extern "C" void kernel_launch(void* const* d_in, const int* in_sizes, int n_in,
                              void* d_out, int out_size) {
    const float* cnn     = (const float*)d_in[0];   // [16,684,32,128]
    const float* cft     = (const float*)d_in[1];   // [16,512,32,128]
    const float* hidden  = (const float*)d_in[2];   // [16,256]
    const float* asum    = (const float*)d_in[3];   // [16,1,32,128]
    const int*   mask    = (const int*)  d_in[4];   // [16,1,32,128]
    const float* cmt     = (const float*)d_in[5];   // [16,32,128,512]
    const float* Wh      = (const float*)d_in[6];   // [512,256]
    const float* bh      = (const float*)d_in[7];   // [512]
    const float* Wconv   = (const float*)d_in[8];   // [512,1,11,11]
    const float* Wattn   = (const float*)d_in[9];   // [512,512]
    const float* Walpha  = (const float*)d_in[10];  // [1,512]
    // d_in[11] = b_alpha: softmax-invariant, skipped

    float* out = (float*)d_out; // [ context 16*684 | alpha 16*4096 | alpha_sum_new 16*4096 ]

    cudaFuncSetAttribute(k_energy, cudaFuncAttributeMaxDynamicSharedMemorySize, SM_TOT);

    k_query<<<Bn, 256>>>(hidden, Wh, bh);
    k_weff<<<128, 256>>>(Wattn, Wconv);
    k_im2col<<<dim3(Hn, Bn), 256>>>(asum);
    k_energy<<<dim3(2, Hn, Bn), 256, SM_TOT>>>(cft, cmt, Walpha);  // 4th launch -> profiled
    k_sm1<<<dim3(Bn, 4), 256>>>(mask);
    k_sm2<<<dim3(Bn, 4), 256>>>(asum, out);
    k_context<<<dim3(Cn, Bn), 256>>>(cnn, out);
}

// round 9
// speedup vs baseline: 1.1867x; 1.1867x over previous
#include <cuda_runtime.h>
#include <cuda_bf16.h>
#include <math.h>
#include <math_constants.h>
#include <cstdint>

#define Bn  16
#define Cn  684
#define Hn  32
#define Wn  128
#define HIDn 256
#define An  512
#define HWn 4096
#define NTAP 121

// ---- scratch (device globals; no allocation allowed) ----
__device__ float    g_query[Bn * An];            // [b][a]
__device__ uint32_t g_weffb[An * 64];            // bf16x2 pairs: [a][tap-pair]
__device__ uint16_t g_X[(size_t)Bn * Hn * 128 * 136];  // im2col, padded rows (LDX=136)
__device__ float    g_epart[2 * Bn * HWn];       // [half][b][pos]
__device__ float    g_energy[Bn * HWn];
__device__ float    g_alpha[Bn * HWn];
__device__ float    g_pm[Bn * 4], g_ps[Bn * 4];

// k_energy SMEM layout (bytes)
#define LDX 136
#define LDW 136
#define SM_X 0
#define SM_W 34816
#define SM_QWA 104448
#define SM_TOT 106496

__device__ __forceinline__ float fast_tanh(float x) {
    float y;
    asm("tanh.approx.f32 %0, %1;" : "=f"(y) : "f"(x));
    return y;
}
__device__ __forceinline__ uint32_t smem_u32(const void* p) {
    uint32_t a;
    asm("{ .reg .u64 t; cvta.to.shared.u64 t, %1; cvt.u32.u64 %0, t; }" : "=r"(a) : "l"(p));
    return a;
}

// ---------------- fused prep: query (0-15) + weff (16-143) + im2col (144-655) ----------------
__global__ void k_prep(const float* __restrict__ hidden,
                       const float* __restrict__ Wh,
                       const float* __restrict__ bh,
                       const float* __restrict__ Wattn,
                       const float* __restrict__ Wconv,
                       const float* __restrict__ asum) {
    const int tid = threadIdx.x;
    if (blockIdx.x < 16) {
        // ---- query = hidden @ Wh^T + bh ----
        __shared__ float sh[HIDn];
        const int b = blockIdx.x;
        if (tid < HIDn) sh[tid] = hidden[b * HIDn + tid];
        __syncthreads();
        for (int a = tid; a < An; a += 256) {
            float s = bh[a];
            const float* w = Wh + (size_t)a * HIDn;
            #pragma unroll 8
            for (int k = 0; k < HIDn; k++) s = fmaf(w[k], sh[k], s);
            g_query[b * An + a] = s;
        }
    } else if (blockIdx.x < 144) {
        // ---- Weff[a][tap] = sum_k Wattn[a][k]*Wconv[k][tap] -> bf16 pairs ----
        __shared__ float sa[4 * 512];
        const int chunk = blockIdx.x - 16;   // 0..127, 4 a-rows each
        for (int i = tid; i < 4 * 512; i += 256)
            sa[i] = Wattn[(size_t)chunk * 4 * 512 + i];
        __syncthreads();
        const int al = tid >> 6, pr = tid & 63;
        float v0 = 0.f, v1 = 0.f;
        const int t0 = pr * 2, t1 = pr * 2 + 1;
        if (t0 < NTAP) {
            #pragma unroll 8
            for (int k = 0; k < 512; k++)
                v0 = fmaf(sa[al * 512 + k], __ldg(&Wconv[(size_t)k * NTAP + t0]), v0);
        }
        if (t1 < NTAP) {
            #pragma unroll 8
            for (int k = 0; k < 512; k++)
                v1 = fmaf(sa[al * 512 + k], __ldg(&Wconv[(size_t)k * NTAP + t1]), v1);
        }
        uint32_t lo = (uint32_t)__bfloat16_as_ushort(__float2bfloat16(v0));
        uint32_t hi = (uint32_t)__bfloat16_as_ushort(__float2bfloat16(v1));
        g_weffb[(chunk * 4 + al) * 64 + pr] = lo | (hi << 16);
    } else {
        // ---- im2col: X[b,h][128 pos][128 taps] bf16 (padded LDX) ----
        const int idx = blockIdx.x - 144;    // 0..511
        const int h = idx % Hn, b = idx / Hn;
        const float* arow = asum + (size_t)b * HWn;
        uint32_t* dst = (uint32_t*)(g_X + ((size_t)(b * Hn + h)) * 128 * LDX);
        for (int o = tid; o < 128 * 64; o += 256) {
            int mm = o >> 6, pr = o & 63;
            uint32_t packed = 0;
            #pragma unroll
            for (int hf = 0; hf < 2; hf++) {
                int k = pr * 2 + hf;
                float v = 0.f;
                if (k < NTAP) {
                    int i = k / 11, j = k % 11;
                    int gh = h - 5 + i, gw = mm - 5 + j;
                    if (gh >= 0 && gh < Hn && gw >= 0 && gw < Wn)
                        v = arow[gh * Wn + gw];
                }
                packed |= ((uint32_t)__bfloat16_as_ushort(__float2bfloat16(v))) << (16 * hf);
            }
            dst[mm * (LDX / 2) + pr] = packed;
        }
    }
}

// ---------------- energy: mma.sync m16n8k16, distance-2 pipeline, SMEM fragments ----------------
// grid (2 a-halves, H, B), 256 threads (8 warps). Warp wid owns positions [16*wid, 16*wid+16).
__global__ void __launch_bounds__(256, 2) k_energy(
    const float* __restrict__ cft,     // [b, A, h, w]
    const float* __restrict__ cmt,     // [b, h, w, A]
    const float* __restrict__ walpha)  // [A]
{
    extern __shared__ char smem[];
    __nv_bfloat16* Xsm = (__nv_bfloat16*)(smem + SM_X);
    __nv_bfloat16* Wsm = (__nv_bfloat16*)(smem + SM_W);
    float2*        QWA = (float2*)(smem + SM_QWA);

    const int half = blockIdx.x, h = blockIdx.y, b = blockIdx.z;
    const int tid = threadIdx.x, wid = tid >> 5, lane = tid & 31;
    const int g = lane >> 2, tig = lane & 3;

    // ---- stage X: plain uint4 copy of pre-built im2col tile (34816 B) ----
    {
        const uint4* src = (const uint4*)(g_X + ((size_t)(b * Hn + h)) * 128 * LDX);
        uint4* dst = (uint4*)Xsm;
        #pragma unroll
        for (int o = tid; o < 2176; o += 256) dst[o] = src[o];
    }
    // ---- stage W half: 256 a-rows x 128 taps bf16 ----
    const uint4* wsrc = (const uint4*)(g_weffb + (size_t)half * 256 * 64);
    for (int o = tid; o < 4096; o += 256) {
        int a = o >> 4, q = o & 15;
        *(uint4*)((char*)Wsm + a * (LDW * 2) + q * 16) = wsrc[o];
    }
    // ---- stage (query, walpha) pairs for this a-half ----
    if (tid < 256)
        QWA[tid] = make_float2(g_query[b * An + half * 256 + tid], walpha[half * 256 + tid]);
    __syncthreads();

    const int pos0 = wid * 16;
    const char* xrow0 = (const char*)Xsm + (pos0 + g) * (LDX * 2);
    const char* xrow1 = (const char*)Xsm + (pos0 + 8 + g) * (LDX * 2);

    const uint32_t a_base = smem_u32(Wsm) + (uint32_t)(lane & 15) * (LDW * 2) + (uint32_t)(lane >> 4) * 16;

    const float* cft_b = cft + ((size_t)b * An + half * 256) * (Hn * Wn) + h * Wn;
    const float* cmt_b = cmt + (((size_t)b * Hn + h) * Wn) * An + half * 256;
    const size_t HW = (size_t)Hn * Wn;

    // triple-buffered epilogue operands (prefetch distance 2)
    float2 cfb[3][2][2];   // [buf][nh][aoff/8]
    float  cmb[3][2][4];   // [buf][nh][c]

    auto load_ops = [&](int buf, int A0L) {
        #pragma unroll
        for (int nh = 0; nh < 2; nh++) {
            const float* p = cft_b + (size_t)(A0L + g) * HW + pos0 + nh * 8 + tig * 2;
            cfb[buf][nh][0] = *(const float2*)p;
            cfb[buf][nh][1] = *(const float2*)(p + 8 * HW);
        }
        #pragma unroll
        for (int nh = 0; nh < 2; nh++) {
            const float* p = cmt_b + (size_t)(pos0 + nh * 8 + tig * 2) * An + A0L + g;
            cmb[buf][nh][0] = __ldg(p);
            cmb[buf][nh][1] = __ldg(p + An);
            cmb[buf][nh][2] = __ldg(p + 8);
            cmb[buf][nh][3] = __ldg(p + An + 8);
        }
    };

    load_ops(0, 0);    // prologue: distance-2 pipeline
    load_ops(1, 16);

    float epos[4] = {0.f, 0.f, 0.f, 0.f};

    #pragma unroll
    for (int mt = 0; mt < 16; mt++) {
        const int A0 = mt * 16;
        const int cur = mt % 3;

        if (mt < 14) load_ops((mt + 2) % 3, A0 + 32);

        const float2 qw0 = QWA[A0 + g], qw1 = QWA[A0 + g + 8];

        float c0[4] = {0.f, 0.f, 0.f, 0.f};
        float c1[4] = {0.f, 0.f, 0.f, 0.f};
        #pragma unroll
        for (int kk = 0; kk < 8; kk++) {
            uint32_t a0r, a1r, a2r, a3r;
            uint32_t addr = a_base + (uint32_t)A0 * (LDW * 2) + (uint32_t)(kk * 32);
            asm volatile("ldmatrix.sync.aligned.m8n8.x4.shared.b16 {%0,%1,%2,%3}, [%4];"
                         : "=r"(a0r), "=r"(a1r), "=r"(a2r), "=r"(a3r) : "r"(addr));
            uint32_t b0a = *(const uint32_t*)(xrow0 + (kk * 16 + tig * 2) * 2);
            uint32_t b0b = *(const uint32_t*)(xrow0 + (kk * 16 + tig * 2 + 8) * 2);
            asm volatile("mma.sync.aligned.m16n8k16.row.col.f32.bf16.bf16.f32 "
                         "{%0,%1,%2,%3}, {%4,%5,%6,%7}, {%8,%9}, {%0,%1,%2,%3};"
                         : "+f"(c0[0]), "+f"(c0[1]), "+f"(c0[2]), "+f"(c0[3])
                         : "r"(a0r), "r"(a1r), "r"(a2r), "r"(a3r),
                           "r"(b0a), "r"(b0b));
            uint32_t b1a = *(const uint32_t*)(xrow1 + (kk * 16 + tig * 2) * 2);
            uint32_t b1b = *(const uint32_t*)(xrow1 + (kk * 16 + tig * 2 + 8) * 2);
            asm volatile("mma.sync.aligned.m16n8k16.row.col.f32.bf16.bf16.f32 "
                         "{%0,%1,%2,%3}, {%4,%5,%6,%7}, {%8,%9}, {%0,%1,%2,%3};"
                         : "+f"(c1[0]), "+f"(c1[1]), "+f"(c1[2]), "+f"(c1[3])
                         : "r"(a0r), "r"(a1r), "r"(a2r), "r"(a3r),
                           "r"(b1a), "r"(b1b));
        }

        // register-resident epilogue on buffer 'cur'
        {
            float s;
            s = c0[0] + cfb[cur][0][0].x + cmb[cur][0][0] + qw0.x; epos[0] = fmaf(qw0.y, fast_tanh(s), epos[0]);
            s = c0[1] + cfb[cur][0][0].y + cmb[cur][0][1] + qw0.x; epos[1] = fmaf(qw0.y, fast_tanh(s), epos[1]);
            s = c0[2] + cfb[cur][0][1].x + cmb[cur][0][2] + qw1.x; epos[0] = fmaf(qw1.y, fast_tanh(s), epos[0]);
            s = c0[3] + cfb[cur][0][1].y + cmb[cur][0][3] + qw1.x; epos[1] = fmaf(qw1.y, fast_tanh(s), epos[1]);
            s = c1[0] + cfb[cur][1][0].x + cmb[cur][1][0] + qw0.x; epos[2] = fmaf(qw0.y, fast_tanh(s), epos[2]);
            s = c1[1] + cfb[cur][1][0].y + cmb[cur][1][1] + qw0.x; epos[3] = fmaf(qw0.y, fast_tanh(s), epos[3]);
            s = c1[2] + cfb[cur][1][1].x + cmb[cur][1][2] + qw1.x; epos[2] = fmaf(qw1.y, fast_tanh(s), epos[2]);
            s = c1[3] + cfb[cur][1][1].y + cmb[cur][1][3] + qw1.x; epos[3] = fmaf(qw1.y, fast_tanh(s), epos[3]);
        }
    }

    // reduce over the 8 g-lanes (lane bits 2-4)
    #pragma unroll
    for (int j = 0; j < 4; j++) {
        epos[j] += __shfl_xor_sync(0xffffffffu, epos[j], 4);
        epos[j] += __shfl_xor_sync(0xffffffffu, epos[j], 8);
        epos[j] += __shfl_xor_sync(0xffffffffu, epos[j], 16);
    }
    if (lane < 4) {
        float* ep = g_epart + ((size_t)half * Bn + b) * HWn + h * Wn + pos0;
        ep[tig * 2]         = epos[0];
        ep[tig * 2 + 1]     = epos[1];
        ep[8 + tig * 2]     = epos[2];
        ep[8 + tig * 2 + 1] = epos[3];
    }
}

// ---------------- softmax stage 1 ----------------
__global__ void k_sm1(const int* __restrict__ mask) {
    __shared__ float red[256];
    const int b = blockIdx.x, qt = blockIdx.y, tid = threadIdx.x;
    const int p0 = qt * 1024;

    float e4[4];
    float mx = -CUDART_INF_F;
    #pragma unroll
    for (int i = 0; i < 4; i++) {
        int p = p0 + i * 256 + tid;
        float e = g_epart[b * HWn + p] + g_epart[(Bn + b) * HWn + p];
        if (mask[b * HWn + p] == 0) e = -CUDART_INF_F;
        e4[i] = e;
        g_energy[b * HWn + p] = e;
        mx = fmaxf(mx, e);
    }
    red[tid] = mx; __syncthreads();
    for (int s = 128; s; s >>= 1) {
        if (tid < s) red[tid] = fmaxf(red[tid], red[tid + s]);
        __syncthreads();
    }
    mx = red[0]; __syncthreads();

    float sum = 0.f;
    #pragma unroll
    for (int i = 0; i < 4; i++) sum += __expf(e4[i] - mx);
    red[tid] = sum; __syncthreads();
    for (int s = 128; s; s >>= 1) {
        if (tid < s) red[tid] += red[tid + s];
        __syncthreads();
    }
    if (tid == 0) { g_pm[b * 4 + qt] = mx; g_ps[b * 4 + qt] = red[0]; }
}

// ---------------- softmax stage 2 ----------------
__global__ void k_sm2(const float* __restrict__ asum, float* __restrict__ out) {
    const int b = blockIdx.x, qt = blockIdx.y, tid = threadIdx.x;
    const int p0 = qt * 1024;

    float m0 = g_pm[b * 4 + 0], m1 = g_pm[b * 4 + 1];
    float m2 = g_pm[b * 4 + 2], m3 = g_pm[b * 4 + 3];
    float m = fmaxf(fmaxf(m0, m1), fmaxf(m2, m3));
    float s = g_ps[b * 4 + 0] * __expf(m0 - m) + g_ps[b * 4 + 1] * __expf(m1 - m)
            + g_ps[b * 4 + 2] * __expf(m2 - m) + g_ps[b * 4 + 3] * __expf(m3 - m);
    const float inv = 1.f / s;

    float* out_alpha = out + Bn * Cn;
    float* out_asum  = out + Bn * Cn + Bn * HWn;
    #pragma unroll
    for (int i = 0; i < 4; i++) {
        int p = p0 + i * 256 + tid;
        float al = __expf(g_energy[b * HWn + p] - m) * inv;
        g_alpha[b * HWn + p] = al;
        out_alpha[b * HWn + p] = al;
        out_asum[b * HWn + p] = al + asum[b * HWn + p];
    }
}

// ---------------- context ----------------
__global__ void k_context(const float* __restrict__ cnn,
                          float* __restrict__ out) {
    const int c = blockIdx.x, b = blockIdx.y, tid = threadIdx.x;
    const float4* row = (const float4*)(cnn + ((size_t)b * Cn + c) * HWn);
    const float4* al  = (const float4*)(g_alpha + b * HWn);
    float s = 0.f;
    #pragma unroll
    for (int it = 0; it < 4; it++) {
        int p = it * 256 + tid;
        float4 r = row[p], a = al[p];
        s = fmaf(a.x, r.x, s); s = fmaf(a.y, r.y, s);
        s = fmaf(a.z, r.z, s); s = fmaf(a.w, r.w, s);
    }
    #pragma unroll
    for (int off = 16; off; off >>= 1)
        s += __shfl_xor_sync(0xffffffffu, s, off);
    __shared__ float red[8];
    if ((tid & 31) == 0) red[tid >> 5] = s;
    __syncthreads();
    if (tid == 0) {
        float t = red[0] + red[1] + red[2] + red[3]
                + red[4] + red[5] + red[6] + red[7];
        out[b * Cn + c] = t;
    }
}

extern "C" void kernel_launch(void* const* d_in, const int* in_sizes, int n_in,
                              void* d_out, int out_size) {
    const float* cnn     = (const float*)d_in[0];   // [16,684,32,128]
    const float* cft     = (const float*)d_in[1];   // [16,512,32,128]
    const float* hidden  = (const float*)d_in[2];   // [16,256]
    const float* asum    = (const float*)d_in[3];   // [16,1,32,128]
    const int*   mask    = (const int*)  d_in[4];   // [16,1,32,128]
    const float* cmt     = (const float*)d_in[5];   // [16,32,128,512]
    const float* Wh      = (const float*)d_in[6];   // [512,256]
    const float* bh      = (const float*)d_in[7];   // [512]
    const float* Wconv   = (const float*)d_in[8];   // [512,1,11,11]
    const float* Wattn   = (const float*)d_in[9];   // [512,512]
    const float* Walpha  = (const float*)d_in[10];  // [1,512]
    // d_in[11] = b_alpha: softmax-invariant, skipped

    float* out = (float*)d_out; // [ context 16*684 | alpha 16*4096 | alpha_sum_new 16*4096 ]

    cudaFuncSetAttribute(k_energy, cudaFuncAttributeMaxDynamicSharedMemorySize, SM_TOT);

    k_prep<<<656, 256>>>(hidden, Wh, bh, Wattn, Wconv, asum);
    k_energy<<<dim3(2, Hn, Bn), 256, SM_TOT>>>(cft, cmt, Walpha);
    k_sm1<<<dim3(Bn, 4), 256>>>(mask);
    k_sm2<<<dim3(Bn, 4), 256>>>(asum, out);
    k_context<<<dim3(Cn, Bn), 256>>>(cnn, out);
}

// round 10
// speedup vs baseline: 1.4259x; 1.2016x over previous
#include <cuda_runtime.h>
#include <cuda_bf16.h>
#include <math.h>
#include <math_constants.h>
#include <cstdint>

#define Bn  16
#define Cn  684
#define Hn  32
#define Wn  128
#define HIDn 256
#define An  512
#define HWn 4096
#define NTAP 121

// ---- scratch (device globals; no allocation allowed) ----
__device__ float    g_query[Bn * An];            // [b][a]
__device__ uint32_t g_weffb[An * 64];            // bf16x2 pairs: [a][tap-pair]
__device__ uint16_t g_X[(size_t)Bn * Hn * 128 * 136];  // im2col, padded rows (LDX=136)
__device__ float    g_epart[2 * Bn * HWn];       // [half][b][pos]
__device__ float    g_energy[Bn * HWn];
__device__ float    g_alpha[Bn * HWn];
__device__ float    g_pm[Bn * 4], g_ps[Bn * 4];

// k_energy SMEM layout (bytes)
#define LDX 136
#define SM_X   0         // 128*272 = 34816
#define SM_W   34816     // 2 bufs * 16*272 = 8704
#define SM_QWA 43520     // 256 float2 = 2048
#define SM_CF  45568     // 2 bufs * 16*528 = 16896   (stride 132 floats)
#define SM_CM  62464     // 2 bufs * 128*80 = 20480   (stride 20 floats)
#define SM_TOT 82944

#define WBUF 4352
#define CFBUF 8448
#define CMBUF 10240

__device__ __forceinline__ float fast_tanh(float x) {
    float y;
    asm("tanh.approx.f32 %0, %1;" : "=f"(y) : "f"(x));
    return y;
}
__device__ __forceinline__ uint32_t smem_u32(const void* p) {
    uint32_t a;
    asm("{ .reg .u64 t; cvta.to.shared.u64 t, %1; cvt.u32.u64 %0, t; }" : "=r"(a) : "l"(p));
    return a;
}
#define CP16(dst, src) \
    asm volatile("cp.async.cg.shared.global [%0], [%1], 16;" :: "r"(dst), "l"(src) : "memory")

// ---------------- fused prep: query (0-15) + weff (16-143) + im2col (144-655) ----------------
__global__ void k_prep(const float* __restrict__ hidden,
                       const float* __restrict__ Wh,
                       const float* __restrict__ bh,
                       const float* __restrict__ Wattn,
                       const float* __restrict__ Wconv,
                       const float* __restrict__ asum) {
    const int tid = threadIdx.x;
    if (blockIdx.x < 16) {
        __shared__ float sh[HIDn];
        const int b = blockIdx.x;
        if (tid < HIDn) sh[tid] = hidden[b * HIDn + tid];
        __syncthreads();
        for (int a = tid; a < An; a += 256) {
            float s = bh[a];
            const float* w = Wh + (size_t)a * HIDn;
            #pragma unroll 8
            for (int k = 0; k < HIDn; k++) s = fmaf(w[k], sh[k], s);
            g_query[b * An + a] = s;
        }
    } else if (blockIdx.x < 144) {
        __shared__ float sa[4 * 512];
        const int chunk = blockIdx.x - 16;
        for (int i = tid; i < 4 * 512; i += 256)
            sa[i] = Wattn[(size_t)chunk * 4 * 512 + i];
        __syncthreads();
        const int al = tid >> 6, pr = tid & 63;
        float v0 = 0.f, v1 = 0.f;
        const int t0 = pr * 2, t1 = pr * 2 + 1;
        if (t0 < NTAP) {
            #pragma unroll 8
            for (int k = 0; k < 512; k++)
                v0 = fmaf(sa[al * 512 + k], __ldg(&Wconv[(size_t)k * NTAP + t0]), v0);
        }
        if (t1 < NTAP) {
            #pragma unroll 8
            for (int k = 0; k < 512; k++)
                v1 = fmaf(sa[al * 512 + k], __ldg(&Wconv[(size_t)k * NTAP + t1]), v1);
        }
        uint32_t lo = (uint32_t)__bfloat16_as_ushort(__float2bfloat16(v0));
        uint32_t hi = (uint32_t)__bfloat16_as_ushort(__float2bfloat16(v1));
        g_weffb[(chunk * 4 + al) * 64 + pr] = lo | (hi << 16);
    } else {
        const int idx = blockIdx.x - 144;
        const int h = idx % Hn, b = idx / Hn;
        const float* arow = asum + (size_t)b * HWn;
        uint32_t* dst = (uint32_t*)(g_X + ((size_t)(b * Hn + h)) * 128 * LDX);
        for (int o = tid; o < 128 * 64; o += 256) {
            int mm = o >> 6, pr = o & 63;
            uint32_t packed = 0;
            #pragma unroll
            for (int hf = 0; hf < 2; hf++) {
                int k = pr * 2 + hf;
                float v = 0.f;
                if (k < NTAP) {
                    int i = k / 11, j = k % 11;
                    int gh = h - 5 + i, gw = mm - 5 + j;
                    if (gh >= 0 && gh < Hn && gw >= 0 && gw < Wn)
                        v = arow[gh * Wn + gw];
                }
                packed |= ((uint32_t)__bfloat16_as_ushort(__float2bfloat16(v))) << (16 * hf);
            }
            dst[mm * (LDX / 2) + pr] = packed;
        }
    }
}

// ---------------- energy: mma.sync + cp.async staged epilogue operands ----------------
// grid (2 a-halves, H, B), 256 threads (8 warps). Warp wid owns positions [16*wid, 16*wid+16).
__global__ void __launch_bounds__(256, 2) k_energy(
    const float* __restrict__ cft,     // [b, A, h, w]
    const float* __restrict__ cmt,     // [b, h, w, A]
    const float* __restrict__ walpha)  // [A]
{
    extern __shared__ char smem[];
    const uint32_t sb = smem_u32(smem);
    const int half = blockIdx.x, h = blockIdx.y, b = blockIdx.z;
    const int tid = threadIdx.x, wid = tid >> 5, lane = tid & 31;
    const int g = lane >> 2, tig = lane & 3;

    // ---- stage X (plain copy) + QWA ----
    {
        const uint4* src = (const uint4*)(g_X + ((size_t)(b * Hn + h)) * 128 * LDX);
        uint4* dst = (uint4*)(smem + SM_X);
        #pragma unroll
        for (int o = tid; o < 2176; o += 256) dst[o] = src[o];
    }
    float2* QWA = (float2*)(smem + SM_QWA);
    QWA[tid] = make_float2(g_query[b * An + half * 256 + tid], walpha[half * 256 + tid]);

    // ---- per-thread staging addresses ----
    const float* cft_b = cft + ((size_t)b * An + half * 256) * (Hn * Wn) + h * Wn;
    const float* cmt_b = cmt + (((size_t)b * Hn + h) * Wn) * An + half * 256;

    const char* wsrc  = (const char*)g_weffb + (((size_t)(half * 256) + (tid >> 4)) * 64 + (size_t)(tid & 15) * 4) * 4;
    const char* cfsrc = (const char*)(cft_b + (size_t)(tid >> 5) * (Hn * Wn)) + (tid & 31) * 16;
    const char* cmsrc = (const char*)(cmt_b + (size_t)(tid >> 2) * An) + (tid & 3) * 16;

    const uint32_t wdst  = sb + SM_W  + (tid >> 4) * 272 + (tid & 15) * 16;
    const uint32_t cfdst = sb + SM_CF + (tid >> 5) * 528 + (tid & 31) * 16;
    const uint32_t cmdst = sb + SM_CM + (tid >> 2) * 80  + (tid & 3) * 16;

    auto stage = [&](int bufsel, int it) {
        const uint32_t ow = bufsel * (uint32_t)WBUF;
        const uint32_t of = bufsel * (uint32_t)CFBUF;
        const uint32_t om = bufsel * (uint32_t)CMBUF;
        CP16(wdst + ow, wsrc + (size_t)it * 4096);
        CP16(cfdst + of,            cfsrc + (size_t)it * 262144);
        CP16(cfdst + of + 8 * 528,  cfsrc + (size_t)it * 262144 + (size_t)8 * Hn * Wn * 4);
        CP16(cmdst + om,            cmsrc + it * 64);
        CP16(cmdst + om + 64 * 80,  cmsrc + it * 64 + (size_t)64 * An * 4);
        asm volatile("cp.async.commit_group;" ::: "memory");
    };

    stage(0, 0);
    __syncthreads();   // X + QWA visible

    // ---- persistent X fragments (both n-halves, 32 regs) ----
    const int pos0 = wid * 16;
    uint32_t bf[2][8][2];
    #pragma unroll
    for (int nh = 0; nh < 2; nh++) {
        const char* xrow = smem + SM_X + (pos0 + nh * 8 + g) * (LDX * 2);
        #pragma unroll
        for (int kk = 0; kk < 8; kk++) {
            bf[nh][kk][0] = *(const uint32_t*)(xrow + (kk * 16 + tig * 2) * 2);
            bf[nh][kk][1] = *(const uint32_t*)(xrow + (kk * 16 + tig * 2 + 8) * 2);
        }
    }

    float epos[4] = {0.f, 0.f, 0.f, 0.f};
    const int p0 = pos0 + tig * 2;

    #pragma unroll
    for (int mt = 0; mt < 16; mt++) {
        const int buf = mt & 1;
        if (mt < 15) {
            stage(buf ^ 1, mt + 1);
            asm volatile("cp.async.wait_group 1;" ::: "memory");
        } else {
            asm volatile("cp.async.wait_group 0;" ::: "memory");
        }
        __syncthreads();

        // ---- GEMM: W tile rows 0..15 in Wbuf[buf] ----
        const uint32_t abase = sb + SM_W + buf * (uint32_t)WBUF + (lane & 15) * 272 + (lane >> 4) * 16;
        float c0[4] = {0.f, 0.f, 0.f, 0.f};
        float c1[4] = {0.f, 0.f, 0.f, 0.f};
        #pragma unroll
        for (int kk = 0; kk < 8; kk++) {
            uint32_t a0r, a1r, a2r, a3r;
            asm volatile("ldmatrix.sync.aligned.m8n8.x4.shared.b16 {%0,%1,%2,%3}, [%4];"
                         : "=r"(a0r), "=r"(a1r), "=r"(a2r), "=r"(a3r) : "r"(abase + kk * 32));
            asm volatile("mma.sync.aligned.m16n8k16.row.col.f32.bf16.bf16.f32 "
                         "{%0,%1,%2,%3}, {%4,%5,%6,%7}, {%8,%9}, {%0,%1,%2,%3};"
                         : "+f"(c0[0]), "+f"(c0[1]), "+f"(c0[2]), "+f"(c0[3])
                         : "r"(a0r), "r"(a1r), "r"(a2r), "r"(a3r),
                           "r"(bf[0][kk][0]), "r"(bf[0][kk][1]));
            asm volatile("mma.sync.aligned.m16n8k16.row.col.f32.bf16.bf16.f32 "
                         "{%0,%1,%2,%3}, {%4,%5,%6,%7}, {%8,%9}, {%0,%1,%2,%3};"
                         : "+f"(c1[0]), "+f"(c1[1]), "+f"(c1[2]), "+f"(c1[3])
                         : "r"(a0r), "r"(a1r), "r"(a2r), "r"(a3r),
                           "r"(bf[1][kk][0]), "r"(bf[1][kk][1]));
        }

        // ---- epilogue: operands from staged SMEM ----
        const float* cfp = (const float*)(smem + SM_CF + buf * CFBUF);
        const float* cmp = (const float*)(smem + SM_CM + buf * CMBUF);
        const int A0l = mt * 16;
        const float2 qw0 = QWA[A0l + g], qw1 = QWA[A0l + g + 8];

        float2 cf00 = *(const float2*)(cfp + g * 132 + p0);
        float2 cf01 = *(const float2*)(cfp + (g + 8) * 132 + p0);
        float2 cf10 = *(const float2*)(cfp + g * 132 + p0 + 8);
        float2 cf11 = *(const float2*)(cfp + (g + 8) * 132 + p0 + 8);

        float cm00a = cmp[p0 * 20 + g],           cm00b = cmp[(p0 + 1) * 20 + g];
        float cm01a = cmp[p0 * 20 + g + 8],       cm01b = cmp[(p0 + 1) * 20 + g + 8];
        float cm10a = cmp[(p0 + 8) * 20 + g],     cm10b = cmp[(p0 + 9) * 20 + g];
        float cm11a = cmp[(p0 + 8) * 20 + g + 8], cm11b = cmp[(p0 + 9) * 20 + g + 8];

        float s;
        s = c0[0] + cf00.x + cm00a + qw0.x; epos[0] = fmaf(qw0.y, fast_tanh(s), epos[0]);
        s = c0[1] + cf00.y + cm00b + qw0.x; epos[1] = fmaf(qw0.y, fast_tanh(s), epos[1]);
        s = c0[2] + cf01.x + cm01a + qw1.x; epos[0] = fmaf(qw1.y, fast_tanh(s), epos[0]);
        s = c0[3] + cf01.y + cm01b + qw1.x; epos[1] = fmaf(qw1.y, fast_tanh(s), epos[1]);
        s = c1[0] + cf10.x + cm10a + qw0.x; epos[2] = fmaf(qw0.y, fast_tanh(s), epos[2]);
        s = c1[1] + cf10.y + cm10b + qw0.x; epos[3] = fmaf(qw0.y, fast_tanh(s), epos[3]);
        s = c1[2] + cf11.x + cm11a + qw1.x; epos[2] = fmaf(qw1.y, fast_tanh(s), epos[2]);
        s = c1[3] + cf11.y + cm11b + qw1.x; epos[3] = fmaf(qw1.y, fast_tanh(s), epos[3]);

        __syncthreads();   // buffer reads complete before next stage overwrites
    }

    // reduce over the 8 g-lanes (lane bits 2-4)
    #pragma unroll
    for (int j = 0; j < 4; j++) {
        epos[j] += __shfl_xor_sync(0xffffffffu, epos[j], 4);
        epos[j] += __shfl_xor_sync(0xffffffffu, epos[j], 8);
        epos[j] += __shfl_xor_sync(0xffffffffu, epos[j], 16);
    }
    if (lane < 4) {
        float* ep = g_epart + ((size_t)half * Bn + b) * HWn + h * Wn + pos0;
        ep[tig * 2]         = epos[0];
        ep[tig * 2 + 1]     = epos[1];
        ep[8 + tig * 2]     = epos[2];
        ep[8 + tig * 2 + 1] = epos[3];
    }
}

// ---------------- softmax stage 1 ----------------
__global__ void k_sm1(const int* __restrict__ mask) {
    __shared__ float red[256];
    const int b = blockIdx.x, qt = blockIdx.y, tid = threadIdx.x;
    const int p0 = qt * 1024;

    float e4[4];
    float mx = -CUDART_INF_F;
    #pragma unroll
    for (int i = 0; i < 4; i++) {
        int p = p0 + i * 256 + tid;
        float e = g_epart[b * HWn + p] + g_epart[(Bn + b) * HWn + p];
        if (mask[b * HWn + p] == 0) e = -CUDART_INF_F;
        e4[i] = e;
        g_energy[b * HWn + p] = e;
        mx = fmaxf(mx, e);
    }
    red[tid] = mx; __syncthreads();
    for (int s = 128; s; s >>= 1) {
        if (tid < s) red[tid] = fmaxf(red[tid], red[tid + s]);
        __syncthreads();
    }
    mx = red[0]; __syncthreads();

    float sum = 0.f;
    #pragma unroll
    for (int i = 0; i < 4; i++) sum += __expf(e4[i] - mx);
    red[tid] = sum; __syncthreads();
    for (int s = 128; s; s >>= 1) {
        if (tid < s) red[tid] += red[tid + s];
        __syncthreads();
    }
    if (tid == 0) { g_pm[b * 4 + qt] = mx; g_ps[b * 4 + qt] = red[0]; }
}

// ---------------- softmax stage 2 ----------------
__global__ void k_sm2(const float* __restrict__ asum, float* __restrict__ out) {
    const int b = blockIdx.x, qt = blockIdx.y, tid = threadIdx.x;
    const int p0 = qt * 1024;

    float m0 = g_pm[b * 4 + 0], m1 = g_pm[b * 4 + 1];
    float m2 = g_pm[b * 4 + 2], m3 = g_pm[b * 4 + 3];
    float m = fmaxf(fmaxf(m0, m1), fmaxf(m2, m3));
    float s = g_ps[b * 4 + 0] * __expf(m0 - m) + g_ps[b * 4 + 1] * __expf(m1 - m)
            + g_ps[b * 4 + 2] * __expf(m2 - m) + g_ps[b * 4 + 3] * __expf(m3 - m);
    const float inv = 1.f / s;

    float* out_alpha = out + Bn * Cn;
    float* out_asum  = out + Bn * Cn + Bn * HWn;
    #pragma unroll
    for (int i = 0; i < 4; i++) {
        int p = p0 + i * 256 + tid;
        float al = __expf(g_energy[b * HWn + p] - m) * inv;
        g_alpha[b * HWn + p] = al;
        out_alpha[b * HWn + p] = al;
        out_asum[b * HWn + p] = al + asum[b * HWn + p];
    }
}

// ---------------- context ----------------
__global__ void k_context(const float* __restrict__ cnn,
                          float* __restrict__ out) {
    const int c = blockIdx.x, b = blockIdx.y, tid = threadIdx.x;
    const float4* row = (const float4*)(cnn + ((size_t)b * Cn + c) * HWn);
    const float4* al  = (const float4*)(g_alpha + b * HWn);
    float s = 0.f;
    #pragma unroll
    for (int it = 0; it < 4; it++) {
        int p = it * 256 + tid;
        float4 r = row[p], a = al[p];
        s = fmaf(a.x, r.x, s); s = fmaf(a.y, r.y, s);
        s = fmaf(a.z, r.z, s); s = fmaf(a.w, r.w, s);
    }
    #pragma unroll
    for (int off = 16; off; off >>= 1)
        s += __shfl_xor_sync(0xffffffffu, s, off);
    __shared__ float red[8];
    if ((tid & 31) == 0) red[tid >> 5] = s;
    __syncthreads();
    if (tid == 0) {
        float t = red[0] + red[1] + red[2] + red[3]
                + red[4] + red[5] + red[6] + red[7];
        out[b * Cn + c] = t;
    }
}

extern "C" void kernel_launch(void* const* d_in, const int* in_sizes, int n_in,
                              void* d_out, int out_size) {
    const float* cnn     = (const float*)d_in[0];   // [16,684,32,128]
    const float* cft     = (const float*)d_in[1];   // [16,512,32,128]
    const float* hidden  = (const float*)d_in[2];   // [16,256]
    const float* asum    = (const float*)d_in[3];   // [16,1,32,128]
    const int*   mask    = (const int*)  d_in[4];   // [16,1,32,128]
    const float* cmt     = (const float*)d_in[5];   // [16,32,128,512]
    const float* Wh      = (const float*)d_in[6];   // [512,256]
    const float* bh      = (const float*)d_in[7];   // [512]
    const float* Wconv   = (const float*)d_in[8];   // [512,1,11,11]
    const float* Wattn   = (const float*)d_in[9];   // [512,512]
    const float* Walpha  = (const float*)d_in[10];  // [1,512]
    // d_in[11] = b_alpha: softmax-invariant, skipped

    float* out = (float*)d_out; // [ context 16*684 | alpha 16*4096 | alpha_sum_new 16*4096 ]

    cudaFuncSetAttribute(k_energy, cudaFuncAttributeMaxDynamicSharedMemorySize, SM_TOT);

    k_prep<<<656, 256>>>(hidden, Wh, bh, Wattn, Wconv, asum);
    k_energy<<<dim3(2, Hn, Bn), 256, SM_TOT>>>(cft, cmt, Walpha);
    k_sm1<<<dim3(Bn, 4), 256>>>(mask);
    k_sm2<<<dim3(Bn, 4), 256>>>(asum, out);
    k_context<<<dim3(Cn, Bn), 256>>>(cnn, out);
}

// round 11
// speedup vs baseline: 1.4310x; 1.0035x over previous
#include <cuda_runtime.h>
#include <cuda_bf16.h>
#include <math.h>
#include <math_constants.h>
#include <cstdint>

#define Bn  16
#define Cn  684
#define Hn  32
#define Wn  128
#define HIDn 256
#define An  512
#define HWn 4096
#define NTAP 121

// ---- scratch (device globals; no allocation allowed) ----
__device__ float    g_query[Bn * An];            // [b][a]
__device__ uint32_t g_weffb[An * 64];            // bf16x2 pairs: [a][tap-pair]
__device__ uint16_t g_X[(size_t)Bn * Hn * 128 * 136];  // im2col, padded rows (LDX=136)
__device__ float    g_epart[2 * Bn * HWn];       // [half][b][pos]
__device__ float    g_energy[Bn * HWn];
__device__ float    g_alpha[Bn * HWn];
__device__ float    g_pm[Bn * 4], g_ps[Bn * 4];

// k_energy SMEM layout (bytes) — triple-buffered pipeline
#define LDX 136
#define SM_X   0         // 128*272 = 34816
#define SM_W   34816     // 3 bufs * 16*272  = 13056
#define SM_QWA 47872     // 256 float2 = 2048
#define SM_CF  49920     // 3 bufs * 16*528  = 25344   (stride 132 floats)
#define SM_CM  75264     // 3 bufs * 128*80  = 30720   (stride 20 floats)
#define SM_TOT 105984

#define WBUF  4352
#define CFBUF 8448
#define CMBUF 10240

__device__ __forceinline__ float fast_tanh(float x) {
    float y;
    asm("tanh.approx.f32 %0, %1;" : "=f"(y) : "f"(x));
    return y;
}
__device__ __forceinline__ uint32_t smem_u32(const void* p) {
    uint32_t a;
    asm("{ .reg .u64 t; cvta.to.shared.u64 t, %1; cvt.u32.u64 %0, t; }" : "=r"(a) : "l"(p));
    return a;
}
#define CP16(dst, src) \
    asm volatile("cp.async.cg.shared.global [%0], [%1], 16;" :: "r"(dst), "l"(src) : "memory")

// ---------------- fused prep: query (0-15) + weff (16-143) + im2col (144-655) ----------------
__global__ void k_prep(const float* __restrict__ hidden,
                       const float* __restrict__ Wh,
                       const float* __restrict__ bh,
                       const float* __restrict__ Wattn,
                       const float* __restrict__ Wconv,
                       const float* __restrict__ asum) {
    const int tid = threadIdx.x;
    if (blockIdx.x < 16) {
        __shared__ float sh[HIDn];
        const int b = blockIdx.x;
        if (tid < HIDn) sh[tid] = hidden[b * HIDn + tid];
        __syncthreads();
        for (int a = tid; a < An; a += 256) {
            float s = bh[a];
            const float* w = Wh + (size_t)a * HIDn;
            #pragma unroll 8
            for (int k = 0; k < HIDn; k++) s = fmaf(w[k], sh[k], s);
            g_query[b * An + a] = s;
        }
    } else if (blockIdx.x < 144) {
        __shared__ float sa[4 * 512];
        const int chunk = blockIdx.x - 16;
        for (int i = tid; i < 4 * 512; i += 256)
            sa[i] = Wattn[(size_t)chunk * 4 * 512 + i];
        __syncthreads();
        const int al = tid >> 6, pr = tid & 63;
        float v0 = 0.f, v1 = 0.f;
        const int t0 = pr * 2, t1 = pr * 2 + 1;
        if (t0 < NTAP) {
            #pragma unroll 8
            for (int k = 0; k < 512; k++)
                v0 = fmaf(sa[al * 512 + k], __ldg(&Wconv[(size_t)k * NTAP + t0]), v0);
        }
        if (t1 < NTAP) {
            #pragma unroll 8
            for (int k = 0; k < 512; k++)
                v1 = fmaf(sa[al * 512 + k], __ldg(&Wconv[(size_t)k * NTAP + t1]), v1);
        }
        uint32_t lo = (uint32_t)__bfloat16_as_ushort(__float2bfloat16(v0));
        uint32_t hi = (uint32_t)__bfloat16_as_ushort(__float2bfloat16(v1));
        g_weffb[(chunk * 4 + al) * 64 + pr] = lo | (hi << 16);
    } else {
        const int idx = blockIdx.x - 144;
        const int h = idx % Hn, b = idx / Hn;
        const float* arow = asum + (size_t)b * HWn;
        uint32_t* dst = (uint32_t*)(g_X + ((size_t)(b * Hn + h)) * 128 * LDX);
        for (int o = tid; o < 128 * 64; o += 256) {
            int mm = o >> 6, pr = o & 63;
            uint32_t packed = 0;
            #pragma unroll
            for (int hf = 0; hf < 2; hf++) {
                int k = pr * 2 + hf;
                float v = 0.f;
                if (k < NTAP) {
                    int i = k / 11, j = k % 11;
                    int gh = h - 5 + i, gw = mm - 5 + j;
                    if (gh >= 0 && gh < Hn && gw >= 0 && gw < Wn)
                        v = arow[gh * Wn + gw];
                }
                packed |= ((uint32_t)__bfloat16_as_ushort(__float2bfloat16(v))) << (16 * hf);
            }
            dst[mm * (LDX / 2) + pr] = packed;
        }
    }
}

// ---------------- energy: mma.sync + depth-3 cp.async pipeline, 1 barrier/iter ----------------
// grid (2 a-halves, H, B), 256 threads (8 warps). Warp wid owns positions [16*wid, 16*wid+16).
__global__ void __launch_bounds__(256, 2) k_energy(
    const float* __restrict__ cft,     // [b, A, h, w]
    const float* __restrict__ cmt,     // [b, h, w, A]
    const float* __restrict__ walpha)  // [A]
{
    extern __shared__ char smem[];
    const uint32_t sb = smem_u32(smem);
    const int half = blockIdx.x, h = blockIdx.y, b = blockIdx.z;
    const int tid = threadIdx.x, wid = tid >> 5, lane = tid & 31;
    const int g = lane >> 2, tig = lane & 3;

    // ---- stage X (plain copy) + QWA ----
    {
        const uint4* src = (const uint4*)(g_X + ((size_t)(b * Hn + h)) * 128 * LDX);
        uint4* dst = (uint4*)(smem + SM_X);
        #pragma unroll
        for (int o = tid; o < 2176; o += 256) dst[o] = src[o];
    }
    float2* QWA = (float2*)(smem + SM_QWA);
    QWA[tid] = make_float2(g_query[b * An + half * 256 + tid], walpha[half * 256 + tid]);

    // ---- per-thread staging addresses ----
    const float* cft_b = cft + ((size_t)b * An + half * 256) * (Hn * Wn) + h * Wn;
    const float* cmt_b = cmt + (((size_t)b * Hn + h) * Wn) * An + half * 256;

    const char* wsrc  = (const char*)g_weffb + (((size_t)(half * 256) + (tid >> 4)) * 64 + (size_t)(tid & 15) * 4) * 4;
    const char* cfsrc = (const char*)(cft_b + (size_t)(tid >> 5) * (Hn * Wn)) + (tid & 31) * 16;
    const char* cmsrc = (const char*)(cmt_b + (size_t)(tid >> 2) * An) + (tid & 3) * 16;

    const uint32_t wdst  = sb + SM_W  + (tid >> 4) * 272 + (tid & 15) * 16;
    const uint32_t cfdst = sb + SM_CF + (tid >> 5) * 528 + (tid & 31) * 16;
    const uint32_t cmdst = sb + SM_CM + (tid >> 2) * 80  + (tid & 3) * 16;

    auto stage = [&](int bufsel, int it) {
        const uint32_t ow = bufsel * (uint32_t)WBUF;
        const uint32_t of = bufsel * (uint32_t)CFBUF;
        const uint32_t om = bufsel * (uint32_t)CMBUF;
        CP16(wdst + ow, wsrc + (size_t)it * 4096);
        CP16(cfdst + of,            cfsrc + (size_t)it * 262144);
        CP16(cfdst + of + 8 * 528,  cfsrc + (size_t)it * 262144 + (size_t)8 * Hn * Wn * 4);
        CP16(cmdst + om,            cmsrc + it * 64);
        CP16(cmdst + om + 64 * 80,  cmsrc + it * 64 + (size_t)64 * An * 4);
        asm volatile("cp.async.commit_group;" ::: "memory");
    };

    stage(0, 0);      // depth-3 prologue
    stage(1, 1);
    __syncthreads();  // X + QWA visible

    // ---- persistent X fragments (both n-halves, 32 regs) ----
    const int pos0 = wid * 16;
    uint32_t bf[2][8][2];
    #pragma unroll
    for (int nh = 0; nh < 2; nh++) {
        const char* xrow = smem + SM_X + (pos0 + nh * 8 + g) * (LDX * 2);
        #pragma unroll
        for (int kk = 0; kk < 8; kk++) {
            bf[nh][kk][0] = *(const uint32_t*)(xrow + (kk * 16 + tig * 2) * 2);
            bf[nh][kk][1] = *(const uint32_t*)(xrow + (kk * 16 + tig * 2 + 8) * 2);
        }
    }

    float epos[4] = {0.f, 0.f, 0.f, 0.f};
    const int p0 = pos0 + tig * 2;

    #pragma unroll
    for (int mt = 0; mt < 16; mt++) {
        const int buf = mt % 3;

        if (mt < 15) asm volatile("cp.async.wait_group 1;" ::: "memory");
        else         asm volatile("cp.async.wait_group 0;" ::: "memory");
        __syncthreads();   // group mt visible to all; prior iter's reads of slot (mt+2)%3 done

        if (mt < 14) stage((mt + 2) % 3, mt + 2);

        // ---- GEMM: W tile rows 0..15 in Wbuf[buf] ----
        const uint32_t abase = sb + SM_W + buf * (uint32_t)WBUF + (lane & 15) * 272 + (lane >> 4) * 16;
        float c0[4] = {0.f, 0.f, 0.f, 0.f};
        float c1[4] = {0.f, 0.f, 0.f, 0.f};
        #pragma unroll
        for (int kk = 0; kk < 8; kk++) {
            uint32_t a0r, a1r, a2r, a3r;
            asm volatile("ldmatrix.sync.aligned.m8n8.x4.shared.b16 {%0,%1,%2,%3}, [%4];"
                         : "=r"(a0r), "=r"(a1r), "=r"(a2r), "=r"(a3r) : "r"(abase + kk * 32));
            asm volatile("mma.sync.aligned.m16n8k16.row.col.f32.bf16.bf16.f32 "
                         "{%0,%1,%2,%3}, {%4,%5,%6,%7}, {%8,%9}, {%0,%1,%2,%3};"
                         : "+f"(c0[0]), "+f"(c0[1]), "+f"(c0[2]), "+f"(c0[3])
                         : "r"(a0r), "r"(a1r), "r"(a2r), "r"(a3r),
                           "r"(bf[0][kk][0]), "r"(bf[0][kk][1]));
            asm volatile("mma.sync.aligned.m16n8k16.row.col.f32.bf16.bf16.f32 "
                         "{%0,%1,%2,%3}, {%4,%5,%6,%7}, {%8,%9}, {%0,%1,%2,%3};"
                         : "+f"(c1[0]), "+f"(c1[1]), "+f"(c1[2]), "+f"(c1[3])
                         : "r"(a0r), "r"(a1r), "r"(a2r), "r"(a3r),
                           "r"(bf[1][kk][0]), "r"(bf[1][kk][1]));
        }

        // ---- epilogue: operands from staged SMEM ----
        const float* cfp = (const float*)(smem + SM_CF + buf * CFBUF);
        const float* cmp = (const float*)(smem + SM_CM + buf * CMBUF);
        const int A0l = mt * 16;
        const float2 qw0 = QWA[A0l + g], qw1 = QWA[A0l + g + 8];

        float2 cf00 = *(const float2*)(cfp + g * 132 + p0);
        float2 cf01 = *(const float2*)(cfp + (g + 8) * 132 + p0);
        float2 cf10 = *(const float2*)(cfp + g * 132 + p0 + 8);
        float2 cf11 = *(const float2*)(cfp + (g + 8) * 132 + p0 + 8);

        float cm00a = cmp[p0 * 20 + g],           cm00b = cmp[(p0 + 1) * 20 + g];
        float cm01a = cmp[p0 * 20 + g + 8],       cm01b = cmp[(p0 + 1) * 20 + g + 8];
        float cm10a = cmp[(p0 + 8) * 20 + g],     cm10b = cmp[(p0 + 9) * 20 + g];
        float cm11a = cmp[(p0 + 8) * 20 + g + 8], cm11b = cmp[(p0 + 9) * 20 + g + 8];

        float s;
        s = c0[0] + cf00.x + cm00a + qw0.x; epos[0] = fmaf(qw0.y, fast_tanh(s), epos[0]);
        s = c0[1] + cf00.y + cm00b + qw0.x; epos[1] = fmaf(qw0.y, fast_tanh(s), epos[1]);
        s = c0[2] + cf01.x + cm01a + qw1.x; epos[0] = fmaf(qw1.y, fast_tanh(s), epos[0]);
        s = c0[3] + cf01.y + cm01b + qw1.x; epos[1] = fmaf(qw1.y, fast_tanh(s), epos[1]);
        s = c1[0] + cf10.x + cm10a + qw0.x; epos[2] = fmaf(qw0.y, fast_tanh(s), epos[2]);
        s = c1[1] + cf10.y + cm10b + qw0.x; epos[3] = fmaf(qw0.y, fast_tanh(s), epos[3]);
        s = c1[2] + cf11.x + cm11a + qw1.x; epos[2] = fmaf(qw1.y, fast_tanh(s), epos[2]);
        s = c1[3] + cf11.y + cm11b + qw1.x; epos[3] = fmaf(qw1.y, fast_tanh(s), epos[3]);
    }

    // reduce over the 8 g-lanes (lane bits 2-4)
    #pragma unroll
    for (int j = 0; j < 4; j++) {
        epos[j] += __shfl_xor_sync(0xffffffffu, epos[j], 4);
        epos[j] += __shfl_xor_sync(0xffffffffu, epos[j], 8);
        epos[j] += __shfl_xor_sync(0xffffffffu, epos[j], 16);
    }
    if (lane < 4) {
        float* ep = g_epart + ((size_t)half * Bn + b) * HWn + h * Wn + pos0;
        ep[tig * 2]         = epos[0];
        ep[tig * 2 + 1]     = epos[1];
        ep[8 + tig * 2]     = epos[2];
        ep[8 + tig * 2 + 1] = epos[3];
    }
}

// ---------------- softmax stage 1 ----------------
__global__ void k_sm1(const int* __restrict__ mask) {
    __shared__ float red[256];
    const int b = blockIdx.x, qt = blockIdx.y, tid = threadIdx.x;
    const int p0 = qt * 1024;

    float e4[4];
    float mx = -CUDART_INF_F;
    #pragma unroll
    for (int i = 0; i < 4; i++) {
        int p = p0 + i * 256 + tid;
        float e = g_epart[b * HWn + p] + g_epart[(Bn + b) * HWn + p];
        if (mask[b * HWn + p] == 0) e = -CUDART_INF_F;
        e4[i] = e;
        g_energy[b * HWn + p] = e;
        mx = fmaxf(mx, e);
    }
    red[tid] = mx; __syncthreads();
    for (int s = 128; s; s >>= 1) {
        if (tid < s) red[tid] = fmaxf(red[tid], red[tid + s]);
        __syncthreads();
    }
    mx = red[0]; __syncthreads();

    float sum = 0.f;
    #pragma unroll
    for (int i = 0; i < 4; i++) sum += __expf(e4[i] - mx);
    red[tid] = sum; __syncthreads();
    for (int s = 128; s; s >>= 1) {
        if (tid < s) red[tid] += red[tid + s];
        __syncthreads();
    }
    if (tid == 0) { g_pm[b * 4 + qt] = mx; g_ps[b * 4 + qt] = red[0]; }
}

// ---------------- softmax stage 2 ----------------
__global__ void k_sm2(const float* __restrict__ asum, float* __restrict__ out) {
    const int b = blockIdx.x, qt = blockIdx.y, tid = threadIdx.x;
    const int p0 = qt * 1024;

    float m0 = g_pm[b * 4 + 0], m1 = g_pm[b * 4 + 1];
    float m2 = g_pm[b * 4 + 2], m3 = g_pm[b * 4 + 3];
    float m = fmaxf(fmaxf(m0, m1), fmaxf(m2, m3));
    float s = g_ps[b * 4 + 0] * __expf(m0 - m) + g_ps[b * 4 + 1] * __expf(m1 - m)
            + g_ps[b * 4 + 2] * __expf(m2 - m) + g_ps[b * 4 + 3] * __expf(m3 - m);
    const float inv = 1.f / s;

    float* out_alpha = out + Bn * Cn;
    float* out_asum  = out + Bn * Cn + Bn * HWn;
    #pragma unroll
    for (int i = 0; i < 4; i++) {
        int p = p0 + i * 256 + tid;
        float al = __expf(g_energy[b * HWn + p] - m) * inv;
        g_alpha[b * HWn + p] = al;
        out_alpha[b * HWn + p] = al;
        out_asum[b * HWn + p] = al + asum[b * HWn + p];
    }
}

// ---------------- context ----------------
__global__ void k_context(const float* __restrict__ cnn,
                          float* __restrict__ out) {
    const int c = blockIdx.x, b = blockIdx.y, tid = threadIdx.x;
    const float4* row = (const float4*)(cnn + ((size_t)b * Cn + c) * HWn);
    const float4* al  = (const float4*)(g_alpha + b * HWn);
    float s = 0.f;
    #pragma unroll
    for (int it = 0; it < 4; it++) {
        int p = it * 256 + tid;
        float4 r = row[p], a = al[p];
        s = fmaf(a.x, r.x, s); s = fmaf(a.y, r.y, s);
        s = fmaf(a.z, r.z, s); s = fmaf(a.w, r.w, s);
    }
    #pragma unroll
    for (int off = 16; off; off >>= 1)
        s += __shfl_xor_sync(0xffffffffu, s, off);
    __shared__ float red[8];
    if ((tid & 31) == 0) red[tid >> 5] = s;
    __syncthreads();
    if (tid == 0) {
        float t = red[0] + red[1] + red[2] + red[3]
                + red[4] + red[5] + red[6] + red[7];
        out[b * Cn + c] = t;
    }
}

extern "C" void kernel_launch(void* const* d_in, const int* in_sizes, int n_in,
                              void* d_out, int out_size) {
    const float* cnn     = (const float*)d_in[0];   // [16,684,32,128]
    const float* cft     = (const float*)d_in[1];   // [16,512,32,128]
    const float* hidden  = (const float*)d_in[2];   // [16,256]
    const float* asum    = (const float*)d_in[3];   // [16,1,32,128]
    const int*   mask    = (const int*)  d_in[4];   // [16,1,32,128]
    const float* cmt     = (const float*)d_in[5];   // [16,32,128,512]
    const float* Wh      = (const float*)d_in[6];   // [512,256]
    const float* bh      = (const float*)d_in[7];   // [512]
    const float* Wconv   = (const float*)d_in[8];   // [512,1,11,11]
    const float* Wattn   = (const float*)d_in[9];   // [512,512]
    const float* Walpha  = (const float*)d_in[10];  // [1,512]
    // d_in[11] = b_alpha: softmax-invariant, skipped

    float* out = (float*)d_out; // [ context 16*684 | alpha 16*4096 | alpha_sum_new 16*4096 ]

    cudaFuncSetAttribute(k_energy, cudaFuncAttributeMaxDynamicSharedMemorySize, SM_TOT);

    k_prep<<<656, 256>>>(hidden, Wh, bh, Wattn, Wconv, asum);
    k_energy<<<dim3(2, Hn, Bn), 256, SM_TOT>>>(cft, cmt, Walpha);
    k_sm1<<<dim3(Bn, 4), 256>>>(mask);
    k_sm2<<<dim3(Bn, 4), 256>>>(asum, out);
    k_context<<<dim3(Cn, Bn), 256>>>(cnn, out);
}